// round 11
// baseline (speedup 1.0000x reference)
#include <cuda_runtime.h>
#include <cstdint>

// Batched Thomas tridiagonal solve, B=2048, N=8192, chunked via diagonal
// dominance (alpha in [0,0.3)). Continuant (D/S) recurrence: 1 FMA/step chain,
// rcp.approx off-chain.
// R7: L=64 chunks (HF=8, HB=28, span 101) -> 52.6KB smem -> 4 blocks/SM
// (16 warps/SM). 8-step tiles + inline f loads keep live state ~75 regs so
// the 128-reg occupancy cap does NOT spill (R6's failure mode).

#define N_COLSK 8192
#define L_OWN   64
#define HF      8
#define SPAN_C  101                 // HF + 64 + 28 + 1; odd pitch -> conflict-free LDS
#define TPB     128
#define NT      12                  // tiles: 11 x 8 steps + 1 x 4 steps

#define SM_F    (TPB * SPAN_C)                  // f slice
#define SM_DUMP (SM_F + SPAN_C + 3)             // dump slots for masked lanes
#define SMEM_FLOATS (SM_DUMP + TPB)
#define SMEM_BYTES  (SMEM_FLOATS * 4)           // 52,640 B -> 4 blocks/SM

__device__ __forceinline__ float frcp(float x) {
    float r; asm("rcp.approx.f32 %0, %1;" : "=f"(r) : "f"(x)); return r;
}

// cp.async 4B; src_sz = 0 zero-fills the destination (OOB handling).
__device__ __forceinline__ void cpa4(unsigned int saddr, const float* g, int src_sz) {
    asm volatile("cp.async.ca.shared.global [%0], [%1], 4, %2;"
                 :: "r"(saddr), "l"(g), "r"(src_sz));
}

// Phase-2 tile: recompute cp/dp from tile-entry checkpoint, back-substitute.
// LEN<=8 keeps cpl/dpl at 16 live registers.
template<int LEN, bool STORE>
__device__ __forceinline__ void tile_bwd(
    const float* __restrict__ sA, const float* __restrict__ fS, int base,
    float cp_in, float dp_in, float& u, float* __restrict__ op)
{
    float cpl[LEN], dpl[LEN];
    float alm = sA[base - 1];
    float sm1 = alm * alm;                       // a_base = alpha[base-1]^2
    float a2  = sA[base];
    float qi  = a2 * a2;
    float dmm, dm, sl, qim1;
    {   // j = 0: fold incoming (cp_in, dp_in); local D~_{-1} = 1
        float alp1 = sA[base + 1];
        float sq1  = alp1 * alp1;
        float bi   = fmaf(a2, qi, 1.0f);
        float D0   = fmaf(-sm1, cp_in, bi);
        float S0   = fmaf(-sm1, dp_in, fS[base]);
        float r    = frcp(D0);
        float cj   = fmaf(2.0f, alp1, sq1);
        cpl[0] = cj * r;
        dpl[0] = S0 * r;
        dmm = 1.0f; dm = D0; sl = S0;
        qim1 = qi; qi = sq1; a2 = alp1;
    }
    #pragma unroll
    for (int j = 1; j < LEN; ++j) {
        float alp1 = sA[base + j + 1];
        float sq1  = alp1 * alp1;
        float bi   = fmaf(a2, qi, 1.0f);
        float cim1 = fmaf(2.0f, a2, qi);
        float t    = (qim1 * cim1) * dmm;
        float dn   = fmaf(bi, dm, -t);
        float sn   = fmaf(-qim1, sl, fS[base + j] * dm);
        float r    = frcp(dn);
        float cj   = fmaf(2.0f, alp1, sq1);
        cpl[j] = (cj * dm) * r;
        dpl[j] = sn * r;
        dmm = dm; dm = dn; sl = sn;
        qim1 = qi; qi = sq1; a2 = alp1;
    }
    #pragma unroll
    for (int j = LEN - 1; j >= 0; --j) {
        u = fmaf(-cpl[j], u, dpl[j]);
        dpl[j] = u;
    }
    if (STORE) {
        float4* o4 = reinterpret_cast<float4*>(op);
        #pragma unroll
        for (int q = 0; q < LEN / 4; ++q)
            o4[q] = make_float4(dpl[4*q], dpl[4*q+1], dpl[4*q+2], dpl[4*q+3]);
    }
}

__global__ __launch_bounds__(TPB, 4)
void thomas_chunk_kernel(const float* __restrict__ alpha,
                         const float* __restrict__ f,
                         float* __restrict__ out)
{
    extern __shared__ float smem[];
    float* fS = smem + SM_F;

    const int tid  = threadIdx.x;
    const int cc   = blockIdx.x;                 // chunk column (0..127)
    const int row0 = blockIdx.y * TPB;
    const int s    = cc * L_OWN;
    const int col0 = s - HF;                     // first staged col (>= -8)

    // ================= cp.async staging (1 col/lane, 128 rows) ==============
    {
        const unsigned int smb  = (unsigned int)__cvta_generic_to_shared(smem);
        const unsigned int dump = smb + (unsigned int)(SM_DUMP + tid) * 4u;

        const bool act = tid < SPAN_C;
        const int  c1  = col0 + tid;
        const int  sz1 = (act && c1 >= 0 && c1 < N_COLSK) ? 4 : 0;
        const int  c1c = max(0, min(c1, N_COLSK - 1));

        const float* g1 = alpha + (size_t)row0 * N_COLSK + c1c;
        unsigned int s1 = act ? (smb + (unsigned int)tid * 4u) : dump;
        const unsigned int step = act ? (SPAN_C * 4u) : 0u;

        #pragma unroll 4
        for (int r = 0; r < TPB; ++r) {
            cpa4(s1, g1, sz1);
            s1 += step; g1 += N_COLSK;
        }
        cpa4(act ? (smb + (unsigned int)(SM_F + tid) * 4u) : dump, f + c1c, sz1);

        asm volatile("cp.async.commit_group;");
        asm volatile("cp.async.wait_group 0;");
    }
    __syncthreads();

    const float* sA = smem + tid * SPAN_C;

    // ================= phase 1: forward continuant sweep =================
    float Dmm = 0.0f, Dm = 1.0f, S = 0.0f;
    float sqim1 = 0.0f;
    float al  = sA[0];
    float sqi = al * al;
    float ckcp[NT], ckdp[NT];

#define FSTEP(RC) do {                                   \
        float alp1 = sA[(RC) + 1];                       \
        float sq1  = alp1 * alp1;                        \
        float bi   = fmaf(al, sqi, 1.0f);                \
        float cim1 = fmaf(2.0f, al, sqi);                \
        float t    = (sqim1 * cim1) * Dmm;               \
        float Dn   = fmaf(bi, Dm, -t);                   \
        float Sn   = fmaf(-sqim1, S, fS[(RC)] * Dm);     \
        Dmm = Dm; Dm = Dn; S = Sn;                       \
        sqim1 = sqi; sqi = sq1; al = alp1;               \
    } while (0)

    #pragma unroll
    for (int rc = 0; rc < HF; ++rc) FSTEP(rc);           // left halo warmup

    #pragma unroll
    for (int k = 0; k < NT - 1; ++k) {                   // tiles 0..10 forward
        float r    = frcp(Dm);
        float cim1 = fmaf(2.0f, al, sqi);                // c_{base-1}
        ckcp[k] = (cim1 * Dmm) * r;
        ckdp[k] = S * r;
        const int base = HF + (k << 3);
        #pragma unroll
        for (int j = 0; j < 8; ++j) FSTEP(base + j);
    }
    {   // checkpoint entering tile 11 (its forward steps recomputed in phase 2)
        float r    = frcp(Dm);
        float cim1 = fmaf(2.0f, al, sqi);
        ckcp[NT-1] = (cim1 * Dmm) * r;
        ckdp[NT-1] = S * r;
    }
#undef FSTEP

    // ================= phase 2: tiles descending, back-substitution =========
    float u = 0.0f;                              // halo cut at top
    float* ob = out + (size_t)(row0 + tid) * N_COLSK + s;

    tile_bwd<4, false>(sA, fS, HF + 88, ckcp[11], ckdp[11], u, nullptr);
    tile_bwd<8, false>(sA, fS, HF + 80, ckcp[10], ckdp[10], u, nullptr);
    tile_bwd<8, false>(sA, fS, HF + 72, ckcp[9],  ckdp[9],  u, nullptr);
    tile_bwd<8, false>(sA, fS, HF + 64, ckcp[8],  ckdp[8],  u, nullptr);
    #pragma unroll
    for (int k = 7; k >= 0; --k)
        tile_bwd<8, true>(sA, fS, HF + (k << 3), ckcp[k], ckdp[k], u, ob + (k << 3));
}

extern "C" void kernel_launch(void* const* d_in, const int* in_sizes, int n_in,
                              void* d_out, int out_size)
{
    const float* alpha = (const float*)d_in[0];
    const float* f     = (const float*)d_in[1];
    float* out         = (float*)d_out;

    static int smem_set = 0;
    if (!smem_set) {
        cudaFuncSetAttribute(thomas_chunk_kernel,
                             cudaFuncAttributeMaxDynamicSharedMemorySize,
                             SMEM_BYTES);
        smem_set = 1;
    }

    dim3 grid(N_COLSK / L_OWN, 2048 / TPB);      // (128, 16)
    thomas_chunk_kernel<<<grid, TPB, SMEM_BYTES>>>(alpha, f, out);
}

// round 12
// speedup vs baseline: 1.2584x; 1.2584x over previous
#include <cuda_runtime.h>
#include <cstdint>

// Batched Thomas tridiagonal solve, B=2048, N=8192, chunked via diagonal
// dominance (alpha in [0,0.3)). Continuant (D/S) recurrence: 1 FMA/step chain,
// rcp.approx off-chain.
// R11: identical compute structure to R7, but __launch_bounds__(TPB, 3):
// occ-4's 128-reg cap forced spills twice (R6/R7, ~175MB of local traffic);
// occ-3 gives ~170 regs -> no spills, 12 warps/SM (1.5x the proven occ-2).

#define N_COLSK 8192
#define L_OWN   64
#define HF      8
#define SPAN_C  101                 // HF + 64 + 28 + 1; odd pitch -> conflict-free LDS
#define TPB     128
#define NT      12                  // tiles: 11 x 8 steps + 1 x 4 steps

#define SM_F    (TPB * SPAN_C)                  // f slice
#define SM_DUMP (SM_F + SPAN_C + 3)             // dump slots for masked lanes
#define SMEM_FLOATS (SM_DUMP + TPB)
#define SMEM_BYTES  (SMEM_FLOATS * 4)           // 52,640 B -> 3 blocks/SM (158KB)

__device__ __forceinline__ float frcp(float x) {
    float r; asm("rcp.approx.f32 %0, %1;" : "=f"(r) : "f"(x)); return r;
}

// cp.async 4B; src_sz = 0 zero-fills the destination (OOB handling).
__device__ __forceinline__ void cpa4(unsigned int saddr, const float* g, int src_sz) {
    asm volatile("cp.async.ca.shared.global [%0], [%1], 4, %2;"
                 :: "r"(saddr), "l"(g), "r"(src_sz));
}

// Phase-2 tile: recompute cp/dp from tile-entry checkpoint, back-substitute.
template<int LEN, bool STORE>
__device__ __forceinline__ void tile_bwd(
    const float* __restrict__ sA, const float* __restrict__ fS, int base,
    float cp_in, float dp_in, float& u, float* __restrict__ op)
{
    float cpl[LEN], dpl[LEN];
    float alm = sA[base - 1];
    float sm1 = alm * alm;                       // a_base = alpha[base-1]^2
    float a2  = sA[base];
    float qi  = a2 * a2;
    float dmm, dm, sl, qim1;
    {   // j = 0: fold incoming (cp_in, dp_in); local D~_{-1} = 1
        float alp1 = sA[base + 1];
        float sq1  = alp1 * alp1;
        float bi   = fmaf(a2, qi, 1.0f);
        float D0   = fmaf(-sm1, cp_in, bi);
        float S0   = fmaf(-sm1, dp_in, fS[base]);
        float r    = frcp(D0);
        float cj   = fmaf(2.0f, alp1, sq1);
        cpl[0] = cj * r;
        dpl[0] = S0 * r;
        dmm = 1.0f; dm = D0; sl = S0;
        qim1 = qi; qi = sq1; a2 = alp1;
    }
    #pragma unroll
    for (int j = 1; j < LEN; ++j) {
        float alp1 = sA[base + j + 1];
        float sq1  = alp1 * alp1;
        float bi   = fmaf(a2, qi, 1.0f);
        float cim1 = fmaf(2.0f, a2, qi);
        float t    = (qim1 * cim1) * dmm;
        float dn   = fmaf(bi, dm, -t);
        float sn   = fmaf(-qim1, sl, fS[base + j] * dm);
        float r    = frcp(dn);
        float cj   = fmaf(2.0f, alp1, sq1);
        cpl[j] = (cj * dm) * r;
        dpl[j] = sn * r;
        dmm = dm; dm = dn; sl = sn;
        qim1 = qi; qi = sq1; a2 = alp1;
    }
    #pragma unroll
    for (int j = LEN - 1; j >= 0; --j) {
        u = fmaf(-cpl[j], u, dpl[j]);
        dpl[j] = u;
    }
    if (STORE) {
        float4* o4 = reinterpret_cast<float4*>(op);
        #pragma unroll
        for (int q = 0; q < LEN / 4; ++q)
            o4[q] = make_float4(dpl[4*q], dpl[4*q+1], dpl[4*q+2], dpl[4*q+3]);
    }
}

__global__ __launch_bounds__(TPB, 3)
void thomas_chunk_kernel(const float* __restrict__ alpha,
                         const float* __restrict__ f,
                         float* __restrict__ out)
{
    extern __shared__ float smem[];
    float* fS = smem + SM_F;

    const int tid  = threadIdx.x;
    const int cc   = blockIdx.x;                 // chunk column (0..127)
    const int row0 = blockIdx.y * TPB;
    const int s    = cc * L_OWN;
    const int col0 = s - HF;                     // first staged col (>= -8)

    // ================= cp.async staging (1 col/lane, 128 rows) ==============
    {
        const unsigned int smb  = (unsigned int)__cvta_generic_to_shared(smem);
        const unsigned int dump = smb + (unsigned int)(SM_DUMP + tid) * 4u;

        const bool act = tid < SPAN_C;
        const int  c1  = col0 + tid;
        const int  sz1 = (act && c1 >= 0 && c1 < N_COLSK) ? 4 : 0;
        const int  c1c = max(0, min(c1, N_COLSK - 1));

        const float* g1 = alpha + (size_t)row0 * N_COLSK + c1c;
        unsigned int s1 = act ? (smb + (unsigned int)tid * 4u) : dump;
        const unsigned int step = act ? (SPAN_C * 4u) : 0u;

        #pragma unroll 4
        for (int r = 0; r < TPB; ++r) {
            cpa4(s1, g1, sz1);
            s1 += step; g1 += N_COLSK;
        }
        cpa4(act ? (smb + (unsigned int)(SM_F + tid) * 4u) : dump, f + c1c, sz1);

        asm volatile("cp.async.commit_group;");
        asm volatile("cp.async.wait_group 0;");
    }
    __syncthreads();

    const float* sA = smem + tid * SPAN_C;

    // ================= phase 1: forward continuant sweep =================
    float Dmm = 0.0f, Dm = 1.0f, S = 0.0f;
    float sqim1 = 0.0f;
    float al  = sA[0];
    float sqi = al * al;
    float ckcp[NT], ckdp[NT];

#define FSTEP(RC) do {                                   \
        float alp1 = sA[(RC) + 1];                       \
        float sq1  = alp1 * alp1;                        \
        float bi   = fmaf(al, sqi, 1.0f);                \
        float cim1 = fmaf(2.0f, al, sqi);                \
        float t    = (sqim1 * cim1) * Dmm;               \
        float Dn   = fmaf(bi, Dm, -t);                   \
        float Sn   = fmaf(-sqim1, S, fS[(RC)] * Dm);     \
        Dmm = Dm; Dm = Dn; S = Sn;                       \
        sqim1 = sqi; sqi = sq1; al = alp1;               \
    } while (0)

    #pragma unroll
    for (int rc = 0; rc < HF; ++rc) FSTEP(rc);           // left halo warmup

    #pragma unroll
    for (int k = 0; k < NT - 1; ++k) {                   // tiles 0..10 forward
        float r    = frcp(Dm);
        float cim1 = fmaf(2.0f, al, sqi);                // c_{base-1}
        ckcp[k] = (cim1 * Dmm) * r;
        ckdp[k] = S * r;
        const int base = HF + (k << 3);
        #pragma unroll
        for (int j = 0; j < 8; ++j) FSTEP(base + j);
    }
    {   // checkpoint entering tile 11 (its forward steps recomputed in phase 2)
        float r    = frcp(Dm);
        float cim1 = fmaf(2.0f, al, sqi);
        ckcp[NT-1] = (cim1 * Dmm) * r;
        ckdp[NT-1] = S * r;
    }
#undef FSTEP

    // ================= phase 2: tiles descending, back-substitution =========
    float u = 0.0f;                              // halo cut at top
    float* ob = out + (size_t)(row0 + tid) * N_COLSK + s;

    tile_bwd<4, false>(sA, fS, HF + 88, ckcp[11], ckdp[11], u, nullptr);
    tile_bwd<8, false>(sA, fS, HF + 80, ckcp[10], ckdp[10], u, nullptr);
    tile_bwd<8, false>(sA, fS, HF + 72, ckcp[9],  ckdp[9],  u, nullptr);
    tile_bwd<8, false>(sA, fS, HF + 64, ckcp[8],  ckdp[8],  u, nullptr);
    #pragma unroll
    for (int k = 7; k >= 0; --k)
        tile_bwd<8, true>(sA, fS, HF + (k << 3), ckcp[k], ckdp[k], u, ob + (k << 3));
}

extern "C" void kernel_launch(void* const* d_in, const int* in_sizes, int n_in,
                              void* d_out, int out_size)
{
    const float* alpha = (const float*)d_in[0];
    const float* f     = (const float*)d_in[1];
    float* out         = (float*)d_out;

    static int smem_set = 0;
    if (!smem_set) {
        cudaFuncSetAttribute(thomas_chunk_kernel,
                             cudaFuncAttributeMaxDynamicSharedMemorySize,
                             SMEM_BYTES);
        smem_set = 1;
    }

    dim3 grid(N_COLSK / L_OWN, 2048 / TPB);      // (128, 16)
    thomas_chunk_kernel<<<grid, TPB, SMEM_BYTES>>>(alpha, f, out);
}

// round 13
// speedup vs baseline: 1.7996x; 1.4300x over previous
#include <cuda_runtime.h>
#include <cstdint>

// Batched Thomas tridiagonal solve, B=2048, N=8192, chunked via diagonal
// dominance (alpha in [0,0.3)). Continuant (D/S) recurrence, rcp.approx
// off the dependence chain.
// R12 = R5's proven 66us structure (L=128, rolled tile loops, checkpoints in
// smem, occ-2, regs~89) with tightened halos HF=8 / HB=16 (span 177->153):
// -11% instructions and DRAM reads. R6/R7/R11 showed occupancy pushes backfire
// via reg caps (spills) or unrolled code bloat; per-warp efficiency wins here.

#define N_COLSK 8192
#define L_OWN   128
#define HF      8
#define HB      16
#define SPAN_C  153                 // HF + 128 + 16 + 1; odd pitch -> conflict-free LDS
#define TPB     128
#define NTILES  9                   // 9 x 16 steps over the 144 post-halo cols
#define TAIL_C  (SPAN_C - TPB)      // 25

#define SM_F    (TPB * SPAN_C)                      // f slice
#define SM_CK   (SM_F + SPAN_C + 3)                 // checkpoints (cp then dp)
#define CKOFF   (NTILES * TPB)
#define SM_DUMP (SM_CK + 2 * NTILES * TPB)          // dump slots for masked lanes
#define SMEM_FLOATS (SM_DUMP + TPB)
#define SMEM_BYTES  (SMEM_FLOATS * 4)               // ~88.7 KB -> 2 blocks/SM

__device__ __forceinline__ float frcp(float x) {
    float r; asm("rcp.approx.f32 %0, %1;" : "=f"(r) : "f"(x)); return r;
}

// cp.async 4B; src_sz = 0 zero-fills the destination (OOB handling).
__device__ __forceinline__ void cpa4(unsigned int saddr, const float* g, int src_sz) {
    asm volatile("cp.async.ca.shared.global [%0], [%1], 4, %2;"
                 :: "r"(saddr), "l"(g), "r"(src_sz));
}

__global__ __launch_bounds__(TPB, 2)
void thomas_chunk_kernel(const float* __restrict__ alpha,
                         const float* __restrict__ f,
                         float* __restrict__ out)
{
    extern __shared__ float smem[];
    float* fS  = smem + SM_F;
    float* ckS = smem + SM_CK;

    const int tid  = threadIdx.x;
    const int cc   = blockIdx.x;                 // chunk column (0..63)
    const int row0 = blockIdx.y * TPB;
    const int s    = cc * L_OWN;
    const int col0 = s - HF;                     // first staged col (>= -8)

    // ================= cp.async staging =================
    {
        const unsigned int smb  = (unsigned int)__cvta_generic_to_shared(smem);
        const unsigned int dump = smb + (unsigned int)(SM_DUMP + tid) * 4u;

        const int c1 = col0 + tid;                       // lane's first column
        const int c2 = col0 + TPB + tid;                 // lane's second column
        const int sz1 = (c1 >= 0 && c1 < N_COLSK) ? 4 : 0;
        const bool l2 = (tid < TAIL_C);
        const int sz2 = (l2 && c2 < N_COLSK) ? 4 : 0;
        const int c1c = max(0, min(c1, N_COLSK - 1));    // clamped (safe addr)
        const int c2c = max(0, min(c2, N_COLSK - 1));

        const float* g1 = alpha + (size_t)row0 * N_COLSK + c1c;
        const float* g2 = alpha + (size_t)row0 * N_COLSK + c2c;
        unsigned int s1 = smb + (unsigned int)tid * 4u;
        unsigned int s2 = l2 ? (smb + (unsigned int)(TPB + tid) * 4u) : dump;
        const unsigned int step2 = l2 ? (SPAN_C * 4u) : 0u;

        #pragma unroll 4
        for (int r = 0; r < TPB; ++r) {
            cpa4(s1, g1, sz1);
            cpa4(s2, g2, sz2);
            s1 += SPAN_C * 4u;
            s2 += step2;
            g1 += N_COLSK; g2 += N_COLSK;
        }
        // f slice (broadcast rhs)
        const unsigned int fsb = smb + SM_F * 4u;
        cpa4(fsb + (unsigned int)tid * 4u, f + c1c, sz1);
        cpa4(l2 ? (fsb + (unsigned int)(TPB + tid) * 4u) : dump, f + c2c, sz2);

        asm volatile("cp.async.commit_group;");
        asm volatile("cp.async.wait_group 0;");
    }
    __syncthreads();

    const float* sA = smem + tid * SPAN_C;

    // ================= phase 1: forward continuant sweep =================
    float Dmm = 0.0f, Dm = 1.0f, S = 0.0f;       // D_{-2}, D_{-1}, S_{-1}
    float sqim1 = 0.0f;                          // alpha[i-1]^2 (halo cut)
    float al  = sA[0];
    float sqi = al * al;

#define FSTEP(RC) do {                                   \
        float alp1 = sA[(RC) + 1];                       \
        float fv   = fS[(RC)];                           \
        float sq1  = alp1 * alp1;                        \
        float bi   = fmaf(al, sqi, 1.0f);                \
        float cim1 = fmaf(2.0f, al, sqi);                \
        float t    = (sqim1 * cim1) * Dmm;               \
        float Dn   = fmaf(bi, Dm, -t);                   \
        float Sn   = fmaf(-sqim1, S, fv * Dm);           \
        Dmm = Dm; Dm = Dn; S = Sn;                       \
        sqim1 = sqi; sqi = sq1; al = alp1;               \
    } while (0)

    #pragma unroll
    for (int rc = 0; rc < HF; ++rc) FSTEP(rc);           // left halo warmup

    for (int k = 0; k < NTILES; ++k) {                   // rolled (I$-friendly)
        // checkpoint (cp, dp) entering this tile (rcp off the chain)
        float r    = frcp(Dm);
        float cim1 = fmaf(2.0f, al, sqi);                // c_{base-1}
        ckS[k * TPB + tid]         = (cim1 * Dmm) * r;   // cp_in
        ckS[CKOFF + k * TPB + tid] = S * r;              // dp_in
        const int base = HF + (k << 4);
        #pragma unroll
        for (int j = 0; j < 16; ++j) FSTEP(base + j);
    }
#undef FSTEP

    // ======= phase 2: per tile (desc): recompute cp/dp, back-substitute ======
    float u = 0.0f;                                      // halo cut at top
    for (int k = NTILES - 1; k >= 0; --k) {              // rolled
        const int base = HF + (k << 4);
        const float cp_in = ckS[k * TPB + tid];
        const float dp_in = ckS[CKOFF + k * TPB + tid];

        float al2 = sA[base];
        float sq2 = al2 * al2;
        float alm = sA[base - 1];
        float sm1 = alm * alm;                           // a_base
        float cpl[16], dpl[16];
        float dmm, dm, sl, qim1, qi, a2;
        {   // j = 0: fold incoming (cp_in, dp_in); local D~_{-1} = 1
            float alp1 = sA[base + 1];
            float fv   = fS[base];
            float sq1  = alp1 * alp1;
            float bi   = fmaf(al2, sq2, 1.0f);
            float D0   = fmaf(-sm1, cp_in, bi);
            float S0   = fmaf(-sm1, dp_in, fv);
            float r    = frcp(D0);
            float cj   = fmaf(2.0f, alp1, sq1);
            cpl[0] = cj * r;
            dpl[0] = S0 * r;
            dmm = 1.0f; dm = D0; sl = S0;
            qim1 = sq2; qi = sq1; a2 = alp1;
        }
        #pragma unroll
        for (int j = 1; j < 16; ++j) {
            float alp1 = sA[base + j + 1];
            float fv   = fS[base + j];
            float sq1  = alp1 * alp1;
            float bi   = fmaf(a2, qi, 1.0f);
            float cim1 = fmaf(2.0f, a2, qi);
            float t    = (qim1 * cim1) * dmm;
            float dn   = fmaf(bi, dm, -t);
            float sn   = fmaf(-qim1, sl, fv * dm);
            float r    = frcp(dn);
            float cj   = fmaf(2.0f, alp1, sq1);
            cpl[j] = (cj * dm) * r;
            dpl[j] = sn * r;
            dmm = dm; dm = dn; sl = sn;
            qim1 = qi; qi = sq1; a2 = alp1;
        }
        #pragma unroll
        for (int j = 15; j >= 0; --j) {
            u = fmaf(-cpl[j], u, dpl[j]);
            dpl[j] = u;
        }
        if (k < 8) {                                     // owned tiles only
            float4* o4 = reinterpret_cast<float4*>(
                out + (size_t)(row0 + tid) * N_COLSK + s + (k << 4));
            o4[0] = make_float4(dpl[0],  dpl[1],  dpl[2],  dpl[3]);
            o4[1] = make_float4(dpl[4],  dpl[5],  dpl[6],  dpl[7]);
            o4[2] = make_float4(dpl[8],  dpl[9],  dpl[10], dpl[11]);
            o4[3] = make_float4(dpl[12], dpl[13], dpl[14], dpl[15]);
        }
    }
}

extern "C" void kernel_launch(void* const* d_in, const int* in_sizes, int n_in,
                              void* d_out, int out_size)
{
    const float* alpha = (const float*)d_in[0];
    const float* f     = (const float*)d_in[1];
    float* out         = (float*)d_out;

    static int smem_set = 0;
    if (!smem_set) {
        cudaFuncSetAttribute(thomas_chunk_kernel,
                             cudaFuncAttributeMaxDynamicSharedMemorySize,
                             SMEM_BYTES);
        smem_set = 1;
    }

    dim3 grid(N_COLSK / L_OWN, 2048 / TPB);              // (64, 16)
    thomas_chunk_kernel<<<grid, TPB, SMEM_BYTES>>>(alpha, f, out);
}